// round 1
// baseline (speedup 1.0000x reference)
#include <cuda_runtime.h>
#include <math.h>

// Problem constants (fixed by the reference: B=8192, V=8, J=32)
constexpr int BB = 8192;
constexpr int VV = 8;
constexpr int JJ = 32;
constexpr int PAIRS = BB * VV;              // 65536 (b,v) problems
constexpr int WARPS_PER_BLOCK = 8;          // one block = one batch's 8 views
constexpr int NBLOCKS = PAIRS / WARPS_PER_BLOCK;  // 8192
constexpr float SCALE_KPS = 0.1f;
constexpr float THRESHOLD = 100.0f;
constexpr float ALPHA = 0.1f;
// THRESHOLD^BETA = 100^0.9
constexpr float T_BETA = 63.095734448019324f;

__device__ float g_partial[NBLOCKS];

__global__ __launch_bounds__(WARPS_PER_BLOCK * 32)
void qpl_main(const float* __restrict__ Kmat,
              const float* __restrict__ cam,
              const float* __restrict__ kps,
              const float* __restrict__ init) {
    const int warp_in_blk = threadIdx.x >> 5;
    const int lane = threadIdx.x & 31;
    const int pair = blockIdx.x * WARPS_PER_BLOCK + warp_in_blk;  // b*V + v
    const int b = pair >> 3;

    // ---- M = K @ cam  (3x4), computed redundantly per lane from uniform loads ----
    const float* Kp = Kmat + (size_t)pair * 9;
    const float* Cp = cam + (size_t)pair * 12;
    const float k0 = Kp[0], k1 = Kp[1], k2 = Kp[2];
    const float k3 = Kp[3], k4 = Kp[4], k5 = Kp[5];
    const float k6 = Kp[6], k7 = Kp[7], k8 = Kp[8];
    float M0[4], M1[4], M2[4];
#pragma unroll
    for (int col = 0; col < 4; col++) {
        const float c0 = Cp[col], c1 = Cp[4 + col], c2 = Cp[8 + col];
        M0[col] = k0 * c0 + k1 * c1 + k2 * c2;
        M1[col] = k3 * c0 + k4 * c1 + k5 * c2;
        M2[col] = k6 * c0 + k7 * c1 + k8 * c2;
    }

    // ---- per-joint work: lane j handles joint j (J == 32) ----
    const float* wp = kps + ((size_t)b * JJ + lane) * 3;
    const float X = wp[0], Y = wp[1], Z = wp[2];
    const float2 ik = reinterpret_cast<const float2*>(init)[(size_t)pair * JJ + lane];

    const float px = M0[0] * X + M0[1] * Y + M0[2] * Z + M0[3];
    const float py = M1[0] * X + M1[1] * Y + M1[2] * Z + M1[3];
    const float pz = M2[0] * X + M2[1] * Y + M2[2] * Z + M2[3];
    const float inv_z = 1.0f / pz;
    const float u = px * inv_z;
    const float w = py * inv_z;

    float pn2 = u * u + w * w;                       // proj fro-norm^2 contribution
    float in2 = ik.x * ik.x + ik.y * ik.y;           // init fro-norm^2 contribution

    float d0 = (u - ik.x) * SCALE_KPS; d0 = d0 * d0;
    float d1 = (w - ik.y) * SCALE_KPS; d1 = d1 * d1;
    if (d0 > THRESHOLD) d0 = powf(d0, ALPHA) * T_BETA;
    if (d1 > THRESHOLD) d1 = powf(d1, ALPHA) * T_BETA;
    float ls = d0 + d1;

    // ---- warp butterfly reduce (3 values) ----
#pragma unroll
    for (int o = 16; o; o >>= 1) {
        pn2 += __shfl_xor_sync(0xFFFFFFFFu, pn2, o);
        in2 += __shfl_xor_sync(0xFFFFFFFFu, in2, o);
        ls  += __shfl_xor_sync(0xFFFFFFFFu, ls,  o);
    }

    __shared__ float sm[WARPS_PER_BLOCK];
    if (lane == 0) {
        const float penal = fabsf(sqrtf(pn2) / sqrtf(in2) - 1.0f);
        sm[warp_in_blk] = penal * ls * 0.5f;
    }
    __syncthreads();
    if (threadIdx.x == 0) {
        float s = 0.0f;
#pragma unroll
        for (int i = 0; i < WARPS_PER_BLOCK; i++) s += sm[i];
        g_partial[blockIdx.x] = s;
    }
}

__global__ __launch_bounds__(256)
void qpl_reduce(float* __restrict__ out) {
    __shared__ float sm[256];
    float s = 0.0f;
    for (int i = threadIdx.x; i < NBLOCKS; i += 256) s += g_partial[i];
    sm[threadIdx.x] = s;
    __syncthreads();
#pragma unroll
    for (int o = 128; o; o >>= 1) {
        if (threadIdx.x < o) sm[threadIdx.x] += sm[threadIdx.x + o];
        __syncthreads();
    }
    if (threadIdx.x == 0) out[0] = sm[0] * (1.0f / (float)PAIRS);
}

extern "C" void kernel_launch(void* const* d_in, const int* in_sizes, int n_in,
                              void* d_out, int out_size) {
    const float* Kmat = (const float*)d_in[0];   // [B,V,3,3]
    const float* cam  = (const float*)d_in[1];   // [B,V,3,4]
    const float* kps  = (const float*)d_in[2];   // [B,J,3]
    const float* init = (const float*)d_in[3];   // [B,V,J,2]
    float* out = (float*)d_out;

    qpl_main<<<NBLOCKS, WARPS_PER_BLOCK * 32>>>(Kmat, cam, kps, init);
    qpl_reduce<<<1, 256>>>(out);
}

// round 3
// speedup vs baseline: 1.5646x; 1.5646x over previous
#include <cuda_runtime.h>
#include <math.h>

// Problem constants (fixed by the reference: B=8192, V=8, J=32)
constexpr int BB = 8192;
constexpr int VV = 8;
constexpr int JJ = 32;
constexpr int PAIRS = BB * VV;                    // 65536 (b,v) problems
constexpr int WARPS_PER_BLOCK = 8;                // one block = one batch's 8 views
constexpr int NBLOCKS = PAIRS / WARPS_PER_BLOCK;  // 8192
constexpr float SCALE_KPS = 0.1f;
constexpr float THRESHOLD = 100.0f;
constexpr float ALPHA = 0.1f;
// THRESHOLD^BETA = 100^0.9
constexpr float T_BETA = 63.095734448019324f;
// fixed-point scale for order-invariant deterministic accumulation
constexpr double FIX = 262144.0;                  // 2^18

__device__ unsigned long long g_accum = 0ull;     // fixed-point grid sum
__device__ unsigned int g_ticket = 0u;            // completion counter

__global__ __launch_bounds__(WARPS_PER_BLOCK * 32)
void qpl_fused(const float* __restrict__ Kmat,
               const float* __restrict__ cam,
               const float* __restrict__ kps,
               const float* __restrict__ init,
               float* __restrict__ out) {
    const int warp_in_blk = threadIdx.x >> 5;
    const int lane = threadIdx.x & 31;
    const int pair = blockIdx.x * WARPS_PER_BLOCK + warp_in_blk;  // b*V + v
    const int b = pair >> 3;

    // ---- M = K @ cam (3x4), redundant per lane from warp-uniform loads ----
    const float* Kp = Kmat + (size_t)pair * 9;
    const float4* Cp4 = reinterpret_cast<const float4*>(cam + (size_t)pair * 12);
    const float k0 = Kp[0], k1 = Kp[1], k2 = Kp[2];
    const float k3 = Kp[3], k4 = Kp[4], k5 = Kp[5];
    const float k6 = Kp[6], k7 = Kp[7], k8 = Kp[8];
    const float4 c0 = Cp4[0];  // cam row 0
    const float4 c1 = Cp4[1];  // cam row 1
    const float4 c2 = Cp4[2];  // cam row 2

    float M0[4], M1[4], M2[4];
    {
        const float r0[4] = {c0.x, c0.y, c0.z, c0.w};
        const float r1[4] = {c1.x, c1.y, c1.z, c1.w};
        const float r2[4] = {c2.x, c2.y, c2.z, c2.w};
#pragma unroll
        for (int col = 0; col < 4; col++) {
            M0[col] = k0 * r0[col] + k1 * r1[col] + k2 * r2[col];
            M1[col] = k3 * r0[col] + k4 * r1[col] + k5 * r2[col];
            M2[col] = k6 * r0[col] + k7 * r1[col] + k8 * r2[col];
        }
    }

    // ---- per-joint work: lane j handles joint j (J == 32) ----
    const float* wp = kps + ((size_t)b * JJ + lane) * 3;
    const float X = wp[0], Y = wp[1], Z = wp[2];
    const float2 ik = reinterpret_cast<const float2*>(init)[(size_t)pair * JJ + lane];

    const float px = M0[0] * X + M0[1] * Y + M0[2] * Z + M0[3];
    const float py = M1[0] * X + M1[1] * Y + M1[2] * Z + M1[3];
    const float pz = M2[0] * X + M2[1] * Y + M2[2] * Z + M2[3];
    const float inv_z = __frcp_rn(pz);
    const float u = px * inv_z;
    const float w = py * inv_z;

    float pn2 = u * u + w * w;              // proj fro-norm^2 contribution
    float in2 = ik.x * ik.x + ik.y * ik.y;  // init fro-norm^2 contribution

    float d0 = (u - ik.x) * SCALE_KPS; d0 = d0 * d0;
    float d1 = (w - ik.y) * SCALE_KPS; d1 = d1 * d1;
    // fast pow: exp2(ALPHA*log2(d)) via MUFU — error ~1e-7 rel, OK vs 1e-3 gate
    if (d0 > THRESHOLD) d0 = __powf(d0, ALPHA) * T_BETA;
    if (d1 > THRESHOLD) d1 = __powf(d1, ALPHA) * T_BETA;
    float ls = d0 + d1;

    // ---- warp butterfly reduce (3 values) ----
#pragma unroll
    for (int o = 16; o; o >>= 1) {
        pn2 += __shfl_xor_sync(0xFFFFFFFFu, pn2, o);
        in2 += __shfl_xor_sync(0xFFFFFFFFu, in2, o);
        ls  += __shfl_xor_sync(0xFFFFFFFFu, ls,  o);
    }

    __shared__ float sm[WARPS_PER_BLOCK];
    if (lane == 0) {
        const float penal = fabsf(__fsqrt_rn(pn2 * __frcp_rn(in2)) - 1.0f);
        sm[warp_in_blk] = penal * ls * 0.5f;
    }
    __syncthreads();

    if (threadIdx.x == 0) {
        float s = 0.0f;
#pragma unroll
        for (int i = 0; i < WARPS_PER_BLOCK; i++) s += sm[i];
        // order-invariant integer accumulation => deterministic grid sum
        const long long q = __double2ll_rn((double)s * FIX);
        atomicAdd(&g_accum, (unsigned long long)q);
        __threadfence();
        const unsigned int t = atomicAdd(&g_ticket, 1u);
        if (t == (unsigned int)(NBLOCKS - 1)) {
            // last block: total is complete; publish and reset for next replay
            const unsigned long long total = atomicAdd(&g_accum, 0ull);
            const double mean = ((double)(long long)total) / FIX / (double)PAIRS;
            out[0] = (float)mean;
            // reset accumulator BEFORE releasing the ticket counter, so the
            // next graph replay can never observe a stale partial sum
            atomicExch(&g_accum, 0ull);
            __threadfence();
            atomicExch(&g_ticket, 0u);
        }
    }
}

extern "C" void kernel_launch(void* const* d_in, const int* in_sizes, int n_in,
                              void* d_out, int out_size) {
    const float* Kmat = (const float*)d_in[0];  // [B,V,3,3]
    const float* cam  = (const float*)d_in[1];  // [B,V,3,4]
    const float* kps  = (const float*)d_in[2];  // [B,J,3]
    const float* init = (const float*)d_in[3];  // [B,V,J,2]
    float* out = (float*)d_out;

    qpl_fused<<<NBLOCKS, WARPS_PER_BLOCK * 32>>>(Kmat, cam, kps, init, out);
}